// round 1
// baseline (speedup 1.0000x reference)
#include <cuda_runtime.h>

// Problem: hidden [4096] f32, encoder_outputs [8192,1,4096] f32
// energies = enc @ hidden  -> softmax over S -> output = enc^T @ attn
// d_out: [0:4096) = output (f32), [4096:12288) = attn (f32)

#define SEQ_LEN 8192
#define HIDDEN  4096
#define H4      (HIDDEN / 4)   // 1024 float4 per row

__device__ float g_energies[SEQ_LEN];

// ---------------- Kernel 1: energies[row] = dot(enc[row], hidden) ----------
__global__ __launch_bounds__(256) void gemv_energies(
    const float* __restrict__ enc, const float* __restrict__ hidden)
{
    int row = blockIdx.x;
    const float4* e4 = reinterpret_cast<const float4*>(enc + (size_t)row * HIDDEN);
    const float4* h4 = reinterpret_cast<const float4*>(hidden);

    float acc = 0.f;
    #pragma unroll 4
    for (int i = threadIdx.x; i < H4; i += 256) {
        float4 a = e4[i];
        float4 b = h4[i];
        acc += a.x * b.x + a.y * b.y + a.z * b.z + a.w * b.w;
    }

    // block reduction
    __shared__ float red[8];
    // warp reduce
    #pragma unroll
    for (int off = 16; off > 0; off >>= 1)
        acc += __shfl_down_sync(0xFFFFFFFFu, acc, off);
    int wid = threadIdx.x >> 5;
    if ((threadIdx.x & 31) == 0) red[wid] = acc;
    __syncthreads();
    if (threadIdx.x < 8) {
        float v = red[threadIdx.x];
        #pragma unroll
        for (int off = 4; off > 0; off >>= 1)
            v += __shfl_down_sync(0xFFu, v, off);
        if (threadIdx.x == 0) g_energies[row] = v;
    }
}

// ---------------- Kernel 2: softmax over 8192 energies, write attn ---------
// Single block, 1024 threads. attn goes to d_out + 4096.
__global__ __launch_bounds__(1024) void softmax_attn(float* __restrict__ attn)
{
    __shared__ float red[32];
    const int tid = threadIdx.x;

    // --- max ---
    float m = -3.4e38f;
    #pragma unroll
    for (int i = tid; i < SEQ_LEN; i += 1024)
        m = fmaxf(m, g_energies[i]);
    #pragma unroll
    for (int off = 16; off > 0; off >>= 1)
        m = fmaxf(m, __shfl_xor_sync(0xFFFFFFFFu, m, off));
    if ((tid & 31) == 0) red[tid >> 5] = m;
    __syncthreads();
    if (tid < 32) {
        float v = red[tid];
        #pragma unroll
        for (int off = 16; off > 0; off >>= 1)
            v = fmaxf(v, __shfl_xor_sync(0xFFFFFFFFu, v, off));
        red[tid] = v;
    }
    __syncthreads();
    float gmax = red[0];
    __syncthreads();

    // --- sum of exp ---
    float s = 0.f;
    #pragma unroll
    for (int i = tid; i < SEQ_LEN; i += 1024)
        s += __expf(g_energies[i] - gmax);
    #pragma unroll
    for (int off = 16; off > 0; off >>= 1)
        s += __shfl_xor_sync(0xFFFFFFFFu, s, off);
    if ((tid & 31) == 0) red[tid >> 5] = s;
    __syncthreads();
    if (tid < 32) {
        float v = red[tid];
        #pragma unroll
        for (int off = 16; off > 0; off >>= 1)
            v += __shfl_xor_sync(0xFFFFFFFFu, v, off);
        red[tid] = v;
    }
    __syncthreads();
    float inv = 1.0f / red[0];

    // --- write attn ---
    #pragma unroll
    for (int i = tid; i < SEQ_LEN; i += 1024)
        attn[i] = __expf(g_energies[i] - gmax) * inv;
}

// ---------------- Kernel 3a: zero-init output region -----------------------
__global__ void zero_out(float* __restrict__ out)
{
    out[blockIdx.x * 256 + threadIdx.x] = 0.f;
}

// ---------------- Kernel 3: output[h] += sum_s attn[s]*enc[s][h] -----------
// grid (HIDDEN/256, SEQ_LEN/ROWS_PER_BLK), 256 threads.
#define ROWS_PER_BLK 256
__global__ __launch_bounds__(256) void weighted_sum(
    const float* __restrict__ enc, const float* __restrict__ attn,
    float* __restrict__ out)
{
    __shared__ float w[ROWS_PER_BLK];
    const int col = blockIdx.x * 256 + threadIdx.x;
    const int r0  = blockIdx.y * ROWS_PER_BLK;

    w[threadIdx.x] = attn[r0 + threadIdx.x];
    __syncthreads();

    float acc = 0.f;
    const float* p = enc + (size_t)r0 * HIDDEN + col;
    #pragma unroll 8
    for (int r = 0; r < ROWS_PER_BLK; ++r)
        acc += w[r] * p[(size_t)r * HIDDEN];

    atomicAdd(&out[col], acc);
}

extern "C" void kernel_launch(void* const* d_in, const int* in_sizes, int n_in,
                              void* d_out, int out_size)
{
    const float* hidden = (const float*)d_in[0];
    const float* enc    = (const float*)d_in[1];
    float* out  = (float*)d_out;            // [0:4096)
    float* attn = (float*)d_out + HIDDEN;   // [4096:12288)

    gemv_energies<<<SEQ_LEN, 256>>>(enc, hidden);
    softmax_attn<<<1, 1024>>>(attn);
    zero_out<<<HIDDEN / 256, 256>>>(out);
    weighted_sum<<<dim3(HIDDEN / 256, SEQ_LEN / ROWS_PER_BLK), 256>>>(enc, attn, out);
}

// round 2
// speedup vs baseline: 1.1607x; 1.1607x over previous
#include <cuda_runtime.h>

// hidden [4096] f32, encoder_outputs [8192,1,4096] f32
// energies = enc @ hidden -> softmax -> output = enc^T @ attn
// d_out: [0:4096) = output, [4096:12288) = attn

#define SEQ_LEN 8192
#define HIDDEN  4096
#define H4      (HIDDEN / 4)

__device__ float g_energies[SEQ_LEN];

// ---- Kernel 1: energies[row] = dot(enc[row], hidden); blocks 0..15 also zero out ----
__global__ __launch_bounds__(256) void gemv_energies(
    const float* __restrict__ enc, const float* __restrict__ hidden,
    float* __restrict__ out)
{
    int row = blockIdx.x;
    if (row < 16) out[row * 256 + threadIdx.x] = 0.f;   // zero output region

    const float4* e4 = reinterpret_cast<const float4*>(enc + (size_t)row * HIDDEN);
    const float4* h4 = reinterpret_cast<const float4*>(hidden);

    float acc = 0.f;
    #pragma unroll 4
    for (int i = threadIdx.x; i < H4; i += 256) {
        float4 a = e4[i];
        float4 b = h4[i];
        acc += a.x * b.x + a.y * b.y + a.z * b.z + a.w * b.w;
    }

    __shared__ float red[8];
    #pragma unroll
    for (int off = 16; off > 0; off >>= 1)
        acc += __shfl_down_sync(0xFFFFFFFFu, acc, off);
    if ((threadIdx.x & 31) == 0) red[threadIdx.x >> 5] = acc;
    __syncthreads();
    if (threadIdx.x < 8) {
        float v = red[threadIdx.x];
        #pragma unroll
        for (int off = 4; off > 0; off >>= 1)
            v += __shfl_down_sync(0xFFu, v, off);
        if (threadIdx.x == 0) g_energies[row] = v;
    }
}

// ---- Kernel 2: softmax over energies, write attn ----
__global__ __launch_bounds__(1024) void softmax_attn(float* __restrict__ attn)
{
    __shared__ float red[32];
    const int tid = threadIdx.x;

    float m = -3.4e38f;
    #pragma unroll
    for (int i = tid; i < SEQ_LEN; i += 1024)
        m = fmaxf(m, g_energies[i]);
    #pragma unroll
    for (int off = 16; off > 0; off >>= 1)
        m = fmaxf(m, __shfl_xor_sync(0xFFFFFFFFu, m, off));
    if ((tid & 31) == 0) red[tid >> 5] = m;
    __syncthreads();
    if (tid < 32) {
        float v = red[tid];
        #pragma unroll
        for (int off = 16; off > 0; off >>= 1)
            v = fmaxf(v, __shfl_xor_sync(0xFFFFFFFFu, v, off));
        red[tid] = v;
    }
    __syncthreads();
    float gmax = red[0];
    __syncthreads();

    float s = 0.f;
    #pragma unroll
    for (int i = tid; i < SEQ_LEN; i += 1024)
        s += __expf(g_energies[i] - gmax);
    #pragma unroll
    for (int off = 16; off > 0; off >>= 1)
        s += __shfl_xor_sync(0xFFFFFFFFu, s, off);
    if ((tid & 31) == 0) red[tid >> 5] = s;
    __syncthreads();
    if (tid < 32) {
        float v = red[tid];
        #pragma unroll
        for (int off = 16; off > 0; off >>= 1)
            v += __shfl_xor_sync(0xFFFFFFFFu, v, off);
        red[tid] = v;
    }
    __syncthreads();
    float inv = 1.0f / red[0];

    #pragma unroll
    for (int i = tid; i < SEQ_LEN; i += 1024)
        attn[i] = __expf(g_energies[i] - gmax) * inv;
}

// ---- Kernel 3: output[h] += sum_s attn[s]*enc[s][h], float4 per thread ----
// block: 256 threads -> 256 float4 = 1024 columns. grid (4, 128), 64 rows/block.
#define ROWS_PER_BLK 64
__global__ __launch_bounds__(256) void weighted_sum(
    const float* __restrict__ enc, const float* __restrict__ attn,
    float* __restrict__ out)
{
    __shared__ float w[ROWS_PER_BLK];
    const int c4 = blockIdx.x * 256 + threadIdx.x;      // float4 column index
    const int r0 = blockIdx.y * ROWS_PER_BLK;

    if (threadIdx.x < ROWS_PER_BLK) w[threadIdx.x] = attn[r0 + threadIdx.x];
    __syncthreads();

    float4 acc = make_float4(0.f, 0.f, 0.f, 0.f);
    const float4* p = reinterpret_cast<const float4*>(enc + (size_t)r0 * HIDDEN) + c4;
    #pragma unroll 16
    for (int r = 0; r < ROWS_PER_BLK; ++r) {
        float4 v = p[(size_t)r * H4];
        float ww = w[r];
        acc.x += ww * v.x;
        acc.y += ww * v.y;
        acc.z += ww * v.z;
        acc.w += ww * v.w;
    }

    float* o = out + c4 * 4;
    atomicAdd(o + 0, acc.x);
    atomicAdd(o + 1, acc.y);
    atomicAdd(o + 2, acc.z);
    atomicAdd(o + 3, acc.w);
}

extern "C" void kernel_launch(void* const* d_in, const int* in_sizes, int n_in,
                              void* d_out, int out_size)
{
    const float* hidden = (const float*)d_in[0];
    const float* enc    = (const float*)d_in[1];
    float* out  = (float*)d_out;
    float* attn = (float*)d_out + HIDDEN;

    gemv_energies<<<SEQ_LEN, 256>>>(enc, hidden, out);
    softmax_attn<<<1, 1024>>>(attn);
    weighted_sum<<<dim3(HIDDEN / 1024, SEQ_LEN / ROWS_PER_BLK), 256>>>(enc, attn, out);
}